// round 8
// baseline (speedup 1.0000x reference)
#include <cuda_runtime.h>

// VQ_86139864089353: per-dimension 1D vector quantization — 2 kernels.
// ze: (B, D, 1) f32 ; e: (K, D) f32.  out: [ z (B*D) f32 | zq (B*D) f32 ]
//
// K1: partial stable ranks (u64 monotone keys), atomicAdd -> final rank.
// K2: per-block scatter {value, orig} into sorted smem table, then per
//     element: binary-search upper_bound + exact fp32 argmin over the
//     4-wide window [i-2, i+1] with reference tie-break (min orig index).

#define BN      262144
#define DDIM    3
#define KK      512
#define NBD     (BN * DDIM)
#define NEL     (BN * DDIM)
#define JPARTS  16
#define JCH     (KK / JPARTS)            // 32

#define MBLK    512
#define MVEC    2
#define MGRID   (NEL / (MBLK * MVEC))    // 768

__device__ int g_rank[DDIM][KK];         // final stable ranks (0 at rest)
__device__ int g_done;                   // finished-blocks counter (0 at rest)

// Monotone (order-preserving) uint32 map of an IEEE754 float.
__device__ __forceinline__ unsigned fkey(float f) {
    unsigned u = __float_as_uint(f);
    return u ^ ((unsigned)((int)u >> 31) | 0x80000000u);
}

// ---------------------------------------------------------------------------
// Kernel 1: partial stable ranks. grid (DDIM, JPARTS) x KK threads.
// key = mono(value):index  ->  (kj < kk) == (vj<vk || (vj==vk && j<k))
// ---------------------------------------------------------------------------
__global__ void vq_rank(const float* __restrict__ e) {
    const int d = blockIdx.x;
    const int p = blockIdx.y;
    const int k = threadIdx.x;

    __shared__ unsigned long long s_k[JCH];
    if (k < JCH) {
        int j = p * JCH + k;
        s_k[k] = ((unsigned long long)fkey(e[j * DDIM + d]) << 16) | (unsigned)j;
    }
    __syncthreads();

    const unsigned long long kv =
        ((unsigned long long)fkey(e[k * DDIM + d]) << 16) | (unsigned)k;
    int r = 0;
#pragma unroll
    for (int j = 0; j < JCH; ++j)
        r += (s_k[j] < kv);
    atomicAdd(&g_rank[d][k], r);
}

// ---------------------------------------------------------------------------
// Kernel 2: scatter-build tables per block + quantize. grid MGRID x MBLK.
// ---------------------------------------------------------------------------
__global__ void __launch_bounds__(MBLK, 4)
vq_main(const float2* __restrict__ ze2, const float* __restrict__ e,
        float* __restrict__ out) {
    __shared__ float2 s_pair[DDIM][KK];   // 12 KB: {sorted value, (float)orig}
    __shared__ int    s_last;

    const int tid = threadIdx.x;
    const int t   = blockIdx.x * MBLK + tid;   // float2 element index

    // Prefetch input (overlaps table build latency).
    float2 xv = ze2[t];

    // Per-block scatter build: MBLK == KK, one k per thread per dim.
#pragma unroll
    for (int d = 0; d < DDIM; ++d) {
        float v = e[tid * DDIM + d];
        int   r = g_rank[d][tid];
        s_pair[d][r] = make_float2(v, (float)tid);
    }
    __syncthreads();      // table ready; also: all g_rank reads consumed

    // Count finished readers; the 768th block will later reset globals.
    if (tid == 0) s_last = (atomicAdd(&g_done, 1) == MGRID - 1);

    // ---------------- quantize 2 elements ----------------
    const int n0 = t * MVEC;
    float xs[MVEC] = {xv.x, xv.y};
    float rz[MVEC], rq[MVEC];

    int d = n0 % 3;
#pragma unroll
    for (int j = 0; j < MVEC; ++j) {
        const float x = xs[j];

        // upper_bound: first i with s_pair[d][i].x > x  (same predicate as
        // the previously-validated scan: advance while value <= x)
        int lo = 0, hi = KK;
        while (lo < hi) {
            int m = (lo + hi) >> 1;
            if (s_pair[d][m].x <= x) lo = m + 1; else hi = m;
        }
        const int i = lo;

        // exact fp32 argmin over sorted window [i-2, i+1], tie -> min orig
        float bestD = __int_as_float(0x7f800000);
        float bestO = 1.0e9f;
        float bestV = 0.0f;
#pragma unroll
        for (int off = -2; off <= 1; ++off) {
            int c = i + off;
            c = c < 0 ? 0 : (c > KK - 1 ? KK - 1 : c);
            float2 p = s_pair[d][c];
            float dx = x - p.x;
            float dd = dx * dx;                  // same fp32 op as reference
            bool take = (dd < bestD) || (dd == bestD && p.y < bestO);
            bestD = take ? dd : bestD;
            bestO = take ? p.y : bestO;
            bestV = take ? p.x : bestV;
        }
        rz[j] = bestO;
        rq[j] = bestV;

        d = (d == 2) ? 0 : d + 1;
    }

    ((float2*)out)[t]         = make_float2(rz[0], rz[1]);
    ((float2*)(out + NBD))[t] = make_float2(rq[0], rq[1]);

    // ---------------- self-clean for next graph replay ----------------
    __syncthreads();                      // publishes s_last to all threads
    if (s_last) {
        for (int i2 = tid; i2 < DDIM * KK; i2 += MBLK)
            ((int*)g_rank)[i2] = 0;
        if (tid == 0) g_done = 0;
    }
}

// ---------------------------------------------------------------------------
extern "C" void kernel_launch(void* const* d_in, const int* in_sizes, int n_in,
                              void* d_out, int out_size) {
    const float* ze = (const float*)d_in[0];   // (B, D, 1)
    const float* e  = (const float*)d_in[1];   // (K, D)
    float* out = (float*)d_out;

    vq_rank<<<dim3(DDIM, JPARTS), KK>>>(e);
    vq_main<<<MGRID, MBLK>>>((const float2*)ze, e, out);
}

// round 9
// speedup vs baseline: 1.1983x; 1.1983x over previous
#include <cuda_runtime.h>

// VQ_86139864089353: per-dim 1D vector quantization — SINGLE kernel, phased.
// ze: (B, D, 1) f32 ; e: (K, D) f32.  out: [ z (B*D) f32 | zq (B*D) f32 ]
//
// Phase A (blocks 0..47): partial stable ranks (u64 monotone keys).
// Phase B (blocks 0..2) : sum ranks, scatter sorted {val,orig}, build LUT.
// Phase C (all blocks)  : LUT+scan -> insertion pos, exact fp32 argmin over
//                         [i-2, i+1] with reference tie-break (min orig).

#define BN      262144
#define DDIM    3
#define KK      512
#define NBD     (BN * DDIM)
#define NEL     (BN * DDIM)
#define NCELL   2048
#define FLO     (-4.0f)
#define FW      (8.0f / (float)NCELL)    // 1/256 (dyadic)
#define FINVW   ((float)NCELL / 8.0f)    // 256   (dyadic)
#define JPARTS  16
#define JCH     (KK / JPARTS)            // 32
#define RBLKS   (DDIM * JPARTS)          // 48

#define MBLK    512
#define MVEC    3
#define MGRID   (NEL / (MBLK * MVEC))    // 512  (all resident at occ>=4)

__device__ int            g_rankp[DDIM][JPARTS][KK];  // plain stores (idempotent)
__device__ float2         g_pair[DDIM][KK];
__device__ unsigned short g_lut[DDIM][NCELL];
__device__ int            g_cnt1, g_cnt2, g_done;     // 0 at rest (self-reset)

// Monotone (order-preserving) uint32 map of an IEEE754 float.
__device__ __forceinline__ unsigned fkey(float f) {
    unsigned u = __float_as_uint(f);
    return u ^ ((unsigned)((int)u >> 31) | 0x80000000u);
}

__global__ void __launch_bounds__(MBLK, 4)
vq_all(const float* __restrict__ ze, const float* __restrict__ e,
       float* __restrict__ out) {
    __shared__ float2             s_pair[DDIM][KK];     // 12 KB
    __shared__ unsigned short     s_lut[DDIM][NCELL];   // 12 KB
    __shared__ unsigned long long s_k[JCH];             // 256 B (phase A)

    const int tid = threadIdx.x;
    const int b   = blockIdx.x;
    const int n0  = b * (MBLK * MVEC) + tid;

    // Prefetch inputs early (coalesced; overlaps build/wait).
    const float x0 = ze[n0];
    const float x1 = ze[n0 + MBLK];
    const float x2 = ze[n0 + 2 * MBLK];

    // ---------------- Phase A: partial stable ranks ----------------
    if (b < RBLKS) {
        const int d = b % DDIM;
        const int p = b / DDIM;
        if (tid < JCH) {
            int j = p * JCH + tid;
            s_k[tid] = ((unsigned long long)fkey(e[j * DDIM + d]) << 16)
                     | (unsigned)j;
        }
        __syncthreads();
        const unsigned long long kv =
            ((unsigned long long)fkey(e[tid * DDIM + d]) << 16) | (unsigned)tid;
        int r = 0;
#pragma unroll
        for (int j = 0; j < JCH; ++j) r += (s_k[j] < kv);
        g_rankp[d][p][tid] = r;
        __threadfence();
        __syncthreads();
        if (tid == 0) atomicAdd(&g_cnt1, 1);
    }

    // ---------------- Phase B: scatter + LUT (blocks 0..2) ----------------
    if (b < DDIM) {
        if (tid == 0) {
            while (*(volatile int*)&g_cnt1 != RBLKS) __nanosleep(64);
        }
        __syncthreads();
        __threadfence();   // acquire

        const int d = b;
        int r = 0;
#pragma unroll
        for (int p = 0; p < JPARTS; ++p) r += g_rankp[d][p][tid];

        float* s_sorted = (float*)s_lut;                 // 2 KB scratch
        short* s_org    = (short*)((char*)s_lut + 2048); // 1 KB scratch
        const float v = e[tid * DDIM + d];
        s_sorted[r] = v;
        s_org[r]    = (short)tid;
        __syncthreads();

        g_pair[d][tid] = make_float2(s_sorted[tid], (float)s_org[tid]);

        // LUT: conservative lower bound on insertion position (guard cell).
        for (int c = tid; c < NCELL; c += MBLK) {
            float edge = FLO + (float)c * FW - FW;
            int lo = 0, hi = KK;
            while (lo < hi) {
                int m = (lo + hi) >> 1;
                if (s_sorted[m] < edge) lo = m + 1; else hi = m;
            }
            g_lut[d][c] = (unsigned short)lo;
        }
        __threadfence();
        __syncthreads();
        if (tid == 0) atomicAdd(&g_cnt2, 1);
    }

    // ---------------- Phase C: wait (cold poll), load tables ----------------
    if (tid == 0) {
        while (*(volatile int*)&g_cnt2 != DDIM) __nanosleep(1024);
    }
    __syncthreads();
    __threadfence();   // acquire

    {
        const float4* src = (const float4*)g_pair;
        float4*       dst = (float4*)s_pair;
        for (int i = tid; i < (int)(DDIM * KK * sizeof(float2) / 16); i += MBLK)
            dst[i] = src[i];
    }
    {
        const uint4* src = (const uint4*)g_lut;
        uint4*       dst = (uint4*)s_lut;
        for (int i = tid; i < (int)(DDIM * NCELL * sizeof(short) / 16); i += MBLK)
            dst[i] = src[i];
    }
    __syncthreads();

    // ---------------- quantize 3 strided elements ----------------
    float xs[MVEC] = {x0, x1, x2};
#pragma unroll
    for (int j = 0; j < MVEC; ++j) {
        const int   n = n0 + j * MBLK;
        const int   d = n % 3;
        const float x = xs[j];

        float tt = fminf(fmaxf((x - FLO) * FINVW, 0.0f), (float)(NCELL - 1));
        int i = s_lut[d][(int)tt];
        while (i < KK && s_pair[d][i].x <= x) ++i;

        // exact fp32 argmin over sorted window [i-2, i+1], tie -> min orig
        float bestD = __int_as_float(0x7f800000);
        float bestO = 1.0e9f;
        float bestV = 0.0f;
#pragma unroll
        for (int off = -2; off <= 1; ++off) {
            int c = i + off;
            c = c < 0 ? 0 : (c > KK - 1 ? KK - 1 : c);
            float2 p = s_pair[d][c];
            float dx = x - p.x;
            float dd = dx * dx;                  // same fp32 op as reference
            bool take = (dd < bestD) || (dd == bestD && p.y < bestO);
            bestD = take ? dd : bestD;
            bestO = take ? p.y : bestO;
            bestV = take ? p.x : bestV;
        }
        out[n]       = bestO;
        out[NBD + n] = bestV;
    }

    // ---------------- self-clean for next graph replay ----------------
    __threadfence();
    __syncthreads();
    if (tid == 0) {
        if (atomicAdd(&g_done, 1) == MGRID - 1) {
            g_cnt1 = 0;
            g_cnt2 = 0;
            __threadfence();
            g_done = 0;
        }
    }
}

// ---------------------------------------------------------------------------
extern "C" void kernel_launch(void* const* d_in, const int* in_sizes, int n_in,
                              void* d_out, int out_size) {
    const float* ze = (const float*)d_in[0];   // (B, D, 1)
    const float* e  = (const float*)d_in[1];   // (K, D)
    float* out = (float*)d_out;

    vq_all<<<MGRID, MBLK>>>(ze, e, out);
}